// round 3
// baseline (speedup 1.0000x reference)
#include <cuda_runtime.h>

#define NPIX 16384
#define NS   64
#define NT   2030        // even
#define NB   64
#define BQ   8           // batches per block
#define SNT  (NS*NT)     // 129920
#define WIN  832         // smem window (floats); max span ~692 -> safe
#define WIN2 (WIN/2)     // 416 float2

// Transposed, pre-masked geometry: [s][pix]
__device__ int   g_tT[NS * NPIX];
__device__ float g_wT[NS * NPIX];
__device__ float g_bmax[NB];

// Tiled transpose [pix][s] -> [s][pix], baking clamp + validity into t/w.
// Also zero-inits g_bmax (runs before das in-stream).
__global__ __launch_bounds__(1024) void prep_kernel(
    const float* __restrict__ wts, const int* __restrict__ tidx)
{
    __shared__ int   ts[32][33];
    __shared__ float ws[32][33];
    const int p0 = blockIdx.x * 32;
    const int s0 = blockIdx.y * 32;
    const int tx = threadIdx.x, ty = threadIdx.y;

    if (blockIdx.x == 0 && blockIdx.y == 0 && ty < 2)
        g_bmax[ty * 32 + tx] = 0.0f;

    int   t = tidx[(p0 + ty) * NS + s0 + tx];
    float w = wts [(p0 + ty) * NS + s0 + tx];
    w = (t >= 0 && t < NT) ? w : 0.0f;
    t = min(max(t, 0), NT - 1);
    ts[ty][tx] = t;
    ws[ty][tx] = w;
    __syncthreads();

    g_tT[(s0 + ty) * NPIX + p0 + tx] = ts[tx][ty];
    g_wT[(s0 + ty) * NPIX + p0 + tx] = ws[tx][ty];
}

__global__ __launch_bounds__(256) void das_kernel(
    const float* __restrict__ sino,   // [NB, NS, NT]
    float*       __restrict__ out)    // [NB*NPIX das | NB*NS*NPIX pixel_interp]
{
    __shared__ float2 win2[BQ][WIN2];   // 26624 B staged sinogram windows
    __shared__ int    red[9];

    const int tid  = threadIdx.x;
    const int lane = tid & 31;
    const int wrp  = tid >> 5;          // 8 warps; warp wq stages batch q=wrp
    const int pix  = blockIdx.x * 256 + tid;
    const int b0   = blockIdx.y * BQ;

    const float2* __restrict__ sino2 = reinterpret_cast<const float2*>(sino);
    const float*  __restrict__ winf  = reinterpret_cast<const float*>(win2);

    float* __restrict__ pib = out + NB * NPIX + (size_t)(b0 * NS) * NPIX + pix;

    float acc[BQ];
    #pragma unroll
    for (int q = 0; q < BQ; ++q) acc[q] = 0.0f;

    // per-warp base for this block's staging batch
    const float2* __restrict__ stage_base =
        sino2 + (size_t)(b0 + wrp) * (SNT / 2);

    for (int s = 0; s < NS; ++s) {
        const int   t = g_tT[s * NPIX + pix];
        const float w = g_wT[s * NPIX + pix];

        // ---- block-min of t (also fences previous iteration's gathers) ----
        int m = t;
        #pragma unroll
        for (int off = 16; off > 0; off >>= 1)
            m = min(m, __shfl_xor_sync(0xffffffffu, m, off));
        if (lane == 0) red[wrp] = m;
        __syncthreads();
        if (tid == 0) {
            int mm = red[0];
            #pragma unroll
            for (int i = 1; i < 8; ++i) mm = min(mm, red[i]);
            red[8] = mm & ~1;            // float2-aligned window start
        }
        __syncthreads();
        const int tmin2 = red[8];

        // ---- stage window: warp wq loads WIN floats of batch b0+wq ----
        {
            const float2* __restrict__ src = stage_base + s * (NT / 2);
            const int j0 = tmin2 >> 1;
            #pragma unroll
            for (int k = 0; k < WIN2 / 32; ++k) {          // 13 iters
                int j  = lane + k * 32;
                int jj = min(j0 + j, NT / 2 - 1);
                win2[wrp][j] = __ldg(src + jj);
            }
        }
        __syncthreads();

        // ---- gather from smem, weight, store, accumulate ----
        const int   off = t - tmin2;     // < WIN by construction
        const int   po  = s * NPIX;
        #pragma unroll
        for (int q = 0; q < BQ; ++q) {
            float v = winf[q * WIN + off] * w;
            acc[q] += v;
            pib[(size_t)q * (NS * NPIX) + po] = v;
        }
    }

    // ---- das = relu(sum), raw store + per-batch max ----
    __shared__ float smax[8][BQ];
    float bm[BQ];
    #pragma unroll
    for (int q = 0; q < BQ; ++q) {
        float d = fmaxf(acc[q], 0.0f);
        out[(size_t)(b0 + q) * NPIX + pix] = d;
        bm[q] = d;
    }
    #pragma unroll
    for (int q = 0; q < BQ; ++q) {
        float mv = bm[q];
        #pragma unroll
        for (int off = 16; off > 0; off >>= 1)
            mv = fmaxf(mv, __shfl_xor_sync(0xffffffffu, mv, off));
        if (lane == 0) smax[wrp][q] = mv;
    }
    __syncthreads();
    if (tid < BQ) {
        float mv = smax[0][tid];
        #pragma unroll
        for (int wq = 1; wq < 8; ++wq) mv = fmaxf(mv, smax[wq][tid]);
        atomicMax(reinterpret_cast<int*>(&g_bmax[b0 + tid]),
                  __float_as_int(mv));
    }
}

__global__ __launch_bounds__(256) void norm_kernel(float* __restrict__ out)
{
    int i = blockIdx.x * blockDim.x + threadIdx.x;
    float4* p = reinterpret_cast<float4*>(out);
    float4 v = p[i];
    int b = (i * 4) >> 14;
    float mm = g_bmax[b];
    float r = (mm > 1e-8f) ? (1.0f / mm) : 1.0f;
    v.x *= r; v.y *= r; v.z *= r; v.w *= r;
    p[i] = v;
}

extern "C" void kernel_launch(void* const* d_in, const int* in_sizes, int n_in,
                              void* d_out, int out_size)
{
    const float* sino = (const float*)d_in[0];
    const float* wts  = (const float*)d_in[1];
    const int*   tidx = (const int*)d_in[2];
    float* out = (float*)d_out;

    dim3 pgrid(NPIX / 32, NS / 32);
    prep_kernel<<<pgrid, dim3(32, 32)>>>(wts, tidx);

    dim3 grid(NPIX / 256, NB / BQ);   // (64, 8) = 512 blocks, 1 wave
    das_kernel<<<grid, 256>>>(sino, out);

    norm_kernel<<<(NB * NPIX / 4) / 256, 256>>>(out);
}

// round 4
// speedup vs baseline: 2.6958x; 2.6958x over previous
#include <cuda_runtime.h>

#define NPIX 16384   // 128*128 ROI pixels
#define NS   64      // sensors
#define NT   2030    // time samples
#define NB   64      // batch
#define BQ   8       // batches per block
#define SNT  (NS*NT) // sinogram batch stride = 129920

// Transposed, pre-masked geometry: [s][pix]
__device__ int   g_tT[NS * NPIX];
__device__ float g_wT[NS * NPIX];
__device__ float g_bmax[NB];

// Tiled transpose [pix][s] -> [s][pix], baking clamp + validity into t/w.
// Also zero-inits g_bmax (runs before das in-stream).
__global__ __launch_bounds__(1024) void prep_kernel(
    const float* __restrict__ wts, const int* __restrict__ tidx)
{
    __shared__ int   ts[32][33];
    __shared__ float ws[32][33];
    const int p0 = blockIdx.x * 32;
    const int s0 = blockIdx.y * 32;
    const int tx = threadIdx.x, ty = threadIdx.y;

    if (blockIdx.x == 0 && blockIdx.y == 0 && ty < 2)
        g_bmax[ty * 32 + tx] = 0.0f;

    int   t = tidx[(p0 + ty) * NS + s0 + tx];
    float w = wts [(p0 + ty) * NS + s0 + tx];
    w = (t >= 0 && t < NT) ? w : 0.0f;
    t = min(max(t, 0), NT - 1);
    ts[ty][tx] = t;
    ws[ty][tx] = w;
    __syncthreads();

    g_tT[(s0 + ty) * NPIX + p0 + tx] = ts[tx][ty];
    g_wT[(s0 + ty) * NPIX + p0 + tx] = ws[tx][ty];
}

// Block = 8 warps = 8 consecutive image rows x 32 columns (8x32 pixel tile).
// Warps of a block share gather sectors (row-to-row t shift ~5 samples),
// collapsing L2 read traffic; all loads/stores stay fully coalesced.
__global__ __launch_bounds__(256) void das_kernel(
    const float* __restrict__ sino,   // [NB, NS, NT]
    float*       __restrict__ out)    // [NB*NPIX das | NB*NS*NPIX pixel_interp]
{
    const int tid  = threadIdx.x;
    const int lane = tid & 31;
    const int wrp  = tid >> 5;                 // 0..7 -> row within tile
    const int xt   = blockIdx.x & 3;           // column tile (32 px)
    const int rg   = blockIdx.x >> 2;          // row group (8 rows)
    const int pix  = (rg * 8 + wrp) * 128 + xt * 32 + lane;
    const int b0   = blockIdx.y * BQ;

    const float* __restrict__ sb = sino + b0 * SNT;
    float* __restrict__ pib = out + NB * NPIX + (size_t)(b0 * NS) * NPIX + pix;

    float acc[BQ];
    #pragma unroll
    for (int q = 0; q < BQ; ++q) acc[q] = 0.0f;

    for (int s = 0; s < NS; ++s) {
        const int   t = g_tT[s * NPIX + pix];
        const float w = g_wT[s * NPIX + pix];
        const float* __restrict__ src = sb + s * NT + t;
        const size_t po = (size_t)s * NPIX;

        #pragma unroll
        for (int q = 0; q < BQ; ++q) {
            float v = __ldg(src + q * SNT) * w;
            acc[q] += v;
            pib[po + (size_t)q * (NS * NPIX)] = v;
        }
    }

    // das = relu(sum), store raw (normalized by norm_kernel)
    float bm[BQ];
    #pragma unroll
    for (int q = 0; q < BQ; ++q) {
        float d = fmaxf(acc[q], 0.0f);
        out[(size_t)(b0 + q) * NPIX + pix] = d;
        bm[q] = d;
    }

    // per-batch block max -> atomicMax (nonneg floats: int ordering works)
    __shared__ float smax[8][BQ];
    #pragma unroll
    for (int q = 0; q < BQ; ++q) {
        float m = bm[q];
        #pragma unroll
        for (int off = 16; off > 0; off >>= 1)
            m = fmaxf(m, __shfl_xor_sync(0xffffffffu, m, off));
        if (lane == 0) smax[wrp][q] = m;
    }
    __syncthreads();
    if (tid < BQ) {
        float m = smax[0][tid];
        #pragma unroll
        for (int wq = 1; wq < 8; ++wq) m = fmaxf(m, smax[wq][tid]);
        atomicMax(reinterpret_cast<int*>(&g_bmax[b0 + tid]),
                  __float_as_int(m));
    }
}

__global__ __launch_bounds__(256) void norm_kernel(float* __restrict__ out)
{
    int i = blockIdx.x * blockDim.x + threadIdx.x;    // 0 .. NB*NPIX/4-1
    float4* p = reinterpret_cast<float4*>(out);
    float4 v = p[i];
    int b = (i * 4) >> 14;                            // / NPIX
    float m = g_bmax[b];
    float r = (m > 1e-8f) ? (1.0f / m) : 1.0f;
    v.x *= r; v.y *= r; v.z *= r; v.w *= r;
    p[i] = v;
}

extern "C" void kernel_launch(void* const* d_in, const int* in_sizes, int n_in,
                              void* d_out, int out_size)
{
    const float* sino = (const float*)d_in[0];   // [64,1,64,2030]
    const float* wts  = (const float*)d_in[1];   // [128,128,64]
    const int*   tidx = (const int*)d_in[2];     // [128,128,64]
    float* out = (float*)d_out;

    dim3 pgrid(NPIX / 32, NS / 32);               // (512, 2)
    prep_kernel<<<pgrid, dim3(32, 32)>>>(wts, tidx);

    dim3 grid(4 * 16, NB / BQ);                   // (64, 8) = 512 blocks
    das_kernel<<<grid, 256>>>(sino, out);

    norm_kernel<<<(NB * NPIX / 4) / 256, 256>>>(out);
}

// round 5
// speedup vs baseline: 2.9683x; 1.1011x over previous
#include <cuda_runtime.h>

#define NPIX 16384   // 128*128 ROI pixels
#define NS   64      // sensors
#define NT   2030    // time samples
#define NB   64      // batch
#define BQ   8       // batches per block
#define SNT  (NS*NT) // sinogram batch stride = 129920

// Tile-order, pre-masked geometry: [s][gidx]
__device__ int   g_tT[NS * NPIX];
__device__ float g_wT[NS * NPIX];
__device__ float g_bmax[NB];

// Tile-order index: block(rg,cg) of 8 rows x 32 cols; warp = 8 rows x 4 cols.
// gidx = blk*256 + gw*32 + (y&7)*4 + (x&3), blk = (y>>3)*4 + (x>>5), gw=(x>>2)&7
__device__ __forceinline__ int gidx_of(int pix) {
    int x = pix & 127, y = pix >> 7;
    return (((y >> 3) << 2) + (x >> 5)) * 256
         + (((x >> 2) & 7) << 5) + ((y & 7) << 2) + (x & 3);
}

// Transpose [pix][s] -> tile-ordered [s][gidx], baking clamp + validity.
// Also zero-inits g_bmax.
__global__ __launch_bounds__(1024) void prep_kernel(
    const float* __restrict__ wts, const int* __restrict__ tidx)
{
    __shared__ int   ts[32][33];
    __shared__ float ws[32][33];
    const int p0 = blockIdx.x * 32;
    const int s0 = blockIdx.y * 32;
    const int tx = threadIdx.x, ty = threadIdx.y;

    if (blockIdx.x == 0 && blockIdx.y == 0 && ty < 2)
        g_bmax[ty * 32 + tx] = 0.0f;

    int   t = tidx[(p0 + ty) * NS + s0 + tx];
    float w = wts [(p0 + ty) * NS + s0 + tx];
    w = (t >= 0 && t < NT) ? w : 0.0f;
    t = min(max(t, 0), NT - 1);
    ts[ty][tx] = t;
    ws[ty][tx] = w;
    __syncthreads();

    const int gi = gidx_of(p0 + tx);
    g_tT[(s0 + ty) * NPIX + gi] = ts[tx][ty];
    g_wT[(s0 + ty) * NPIX + gi] = ws[tx][ty];
}

__global__ __launch_bounds__(256) void das_kernel(
    const float* __restrict__ sino,   // [NB, NS, NT]
    float*       __restrict__ out)    // [NB*NPIX das | NB*NS*NPIX pixel_interp]
{
    __shared__ float stg[BQ][256];    // 8 KB restage buffer (XOR-swizzled)
    __shared__ float smax[8][BQ];

    const int tid = threadIdx.x;
    const int l   = tid & 31;
    const int gw  = tid >> 5;              // warp id (gather: col-group; store: row)
    const int cg  = blockIdx.x & 3;        // col group (32 px)
    const int rg  = blockIdx.x >> 2;       // row group (8 rows)
    const int b0  = blockIdx.y * BQ;

    // gather-role pixel (tile order)
    const int y   = rg * 8 + (l >> 2);
    const int x   = cg * 32 + gw * 4 + (l & 3);
    const int pix = y * 128 + x;
    const int gidx = blockIdx.x * 256 + tid;

    // store-role address: warp gw stores row (rg*8+gw), lane l -> col cg*32+l
    const int spix = (rg * 8 + gw) * 128 + cg * 32 + l;
    // conflict-free LDS index for store role (bank = (l&3) + 4*(gw^(l>>2)))
    const int rd_cell = ((l >> 2) << 5) + (((gw << 2) + (l & 3)) ^ ((l >> 2) << 2));
    // conflict-free STS index for gather role (bank = l ^ 4gw)
    const int wr_cell = (gw << 5) + (l ^ (gw << 2));

    const float* __restrict__ sb = sino + b0 * SNT;
    float* __restrict__ pib = out + NB * NPIX + (size_t)(b0 * NS) * NPIX + spix;

    float acc[BQ];
    #pragma unroll
    for (int q = 0; q < BQ; ++q) acc[q] = 0.0f;

    for (int s = 0; s < NS; ++s) {
        const int   t = g_tT[s * NPIX + gidx];
        const float w = g_wT[s * NPIX + gidx];
        const float* __restrict__ src = sb + s * NT + t;

        float v[BQ];
        #pragma unroll
        for (int q = 0; q < BQ; ++q) {
            v[q] = __ldg(src + q * SNT) * w;   // ~2.3-line gathers (tile spread)
            acc[q] += v[q];
        }

        __syncthreads();                       // prev iteration's LDS done
        #pragma unroll
        for (int q = 0; q < BQ; ++q) stg[q][wr_cell] = v[q];
        __syncthreads();

        const size_t po = (size_t)s * NPIX;
        #pragma unroll
        for (int q = 0; q < BQ; ++q)
            pib[po + (size_t)q * (NS * NPIX)] = stg[q][rd_cell];  // coalesced rows
    }

    // das = relu(sum), raw store (scattered 4-px segments; once) + per-batch max
    float bm[BQ];
    #pragma unroll
    for (int q = 0; q < BQ; ++q) {
        float d = fmaxf(acc[q], 0.0f);
        out[(size_t)(b0 + q) * NPIX + pix] = d;
        bm[q] = d;
    }
    #pragma unroll
    for (int q = 0; q < BQ; ++q) {
        float m = bm[q];
        #pragma unroll
        for (int off = 16; off > 0; off >>= 1)
            m = fmaxf(m, __shfl_xor_sync(0xffffffffu, m, off));
        if (l == 0) smax[gw][q] = m;
    }
    __syncthreads();
    if (tid < BQ) {
        float m = smax[0][tid];
        #pragma unroll
        for (int wq = 1; wq < 8; ++wq) m = fmaxf(m, smax[wq][tid]);
        atomicMax(reinterpret_cast<int*>(&g_bmax[b0 + tid]),
                  __float_as_int(m));
    }
}

__global__ __launch_bounds__(256) void norm_kernel(float* __restrict__ out)
{
    int i = blockIdx.x * blockDim.x + threadIdx.x;
    float4* p = reinterpret_cast<float4*>(out);
    float4 v = p[i];
    int b = (i * 4) >> 14;
    float m = g_bmax[b];
    float r = (m > 1e-8f) ? (1.0f / m) : 1.0f;
    v.x *= r; v.y *= r; v.z *= r; v.w *= r;
    p[i] = v;
}

extern "C" void kernel_launch(void* const* d_in, const int* in_sizes, int n_in,
                              void* d_out, int out_size)
{
    const float* sino = (const float*)d_in[0];   // [64,1,64,2030]
    const float* wts  = (const float*)d_in[1];   // [128,128,64]
    const int*   tidx = (const int*)d_in[2];     // [128,128,64]
    float* out = (float*)d_out;

    dim3 pgrid(NPIX / 32, NS / 32);               // (512, 2)
    prep_kernel<<<pgrid, dim3(32, 32)>>>(wts, tidx);

    dim3 grid(64, NB / BQ);                       // 512 blocks, 1 wave
    das_kernel<<<grid, 256>>>(sino, out);

    norm_kernel<<<(NB * NPIX / 4) / 256, 256>>>(out);
}